// round 11
// baseline (speedup 1.0000x reference)
#include <cuda_runtime.h>
#include <math.h>

#define B_   2
#define S_   2048
#define DM_  1024
#define H_   16
#define D_   64
#define MTOT (B_ * S_)   // 4096

// Scratch (no cudaMalloc allowed).
__device__ float g_q[B_ * S_ * DM_];
__device__ float g_k[B_ * S_ * DM_];
__device__ float g_v[B_ * S_ * DM_];
__device__ float g_attn[B_ * S_ * DM_];
__device__ float g_psum[B_ * H_ * S_ * 16];   // per-(row, col-tile) partial exp sums

typedef unsigned long long u64;

// ---- Blackwell packed fp32 helpers (fma.rn.f32x2 — 2 FMAs per issue) ------
__device__ __forceinline__ u64 pack2(float x) {
    u64 r; asm("mov.b64 %0, {%1, %1};" : "=l"(r) : "f"(x)); return r;
}
__device__ __forceinline__ void ffma2(u64& d, u64 a, u64 b) {
    asm("fma.rn.f32x2 %0, %1, %2, %0;" : "+l"(d) : "l"(a), "l"(b));
}
__device__ __forceinline__ void unpack2(float& lo, float& hi, u64 v) {
    asm("mov.b64 {%0, %1}, %2;" : "=f"(lo), "=f"(hi) : "l"(v));
}

// ---------------------------------------------------------------------------
// GEMM + bias body: C[4096,1024] = A[4096,1024] @ W[1024,1024] + bias.
// 64x128 tile, 256 threads, 4x8 per-thread tile, packed f32x2 accumulation.
// Double-buffered smem ping-pong hides global-load latency behind FFMA2s.
// ---------------------------------------------------------------------------
__device__ __forceinline__ void gemm_bias_body(
    const float* __restrict__ A, const float* __restrict__ W,
    const float* __restrict__ bias, float* __restrict__ C) {
    __shared__ float As[2][64][16];    // [buf][m][k]
    __shared__ float Bs[2][16][128];   // [buf][k][n]
    const int tid = threadIdx.x;
    const int tx = tid & 15, ty = tid >> 4;
    const int row0 = blockIdx.y * 64, col0 = blockIdx.x * 128;
    const int lm = tid >> 2, lk4 = (tid & 3) << 2;   // A loader
    const int lkb = tid >> 4, ln8 = (tid & 15) << 3; // B loader

    const float* aptr = &A[(size_t)(row0 + lm) * DM_ + lk4];
    const float* wptr = &W[(size_t)lkb * DM_ + col0 + ln8];

    u64 acc[4][4];
#pragma unroll
    for (int i = 0; i < 4; i++)
#pragma unroll
        for (int p = 0; p < 4; p++) acc[i][p] = 0ull;

    // Prologue: load tile 0 into buffer 0.
    *(float4*)&As[0][lm][lk4]       = *(const float4*)aptr;
    *(float4*)&Bs[0][lkb][ln8]      = *(const float4*)wptr;
    *(float4*)&Bs[0][lkb][ln8 + 4]  = *(const float4*)(wptr + 4);
    __syncthreads();

    int buf = 0;
    for (int kt = 0; kt < DM_; kt += 16) {
        // Issue loads for next tile into the other buffer (no barrier yet).
        if (kt + 16 < DM_) {
            const float* an = aptr + kt + 16;
            const float* wn = wptr + (size_t)(kt + 16) * DM_;
            *(float4*)&As[buf ^ 1][lm][lk4]      = *(const float4*)an;
            *(float4*)&Bs[buf ^ 1][lkb][ln8]     = *(const float4*)wn;
            *(float4*)&Bs[buf ^ 1][lkb][ln8 + 4] = *(const float4*)(wn + 4);
        }
        // Compute on current buffer.
#pragma unroll
        for (int k = 0; k < 16; k++) {
            u64 a2[4];
#pragma unroll
            for (int i = 0; i < 4; i++) a2[i] = pack2(As[buf][ty * 4 + i][k]);
            const u64* bp = (const u64*)&Bs[buf][k][tx * 8];
            ulonglong2 bb0 = *(const ulonglong2*)bp;
            ulonglong2 bb1 = *(const ulonglong2*)(bp + 2);
            u64 b2[4] = {bb0.x, bb0.y, bb1.x, bb1.y};
#pragma unroll
            for (int i = 0; i < 4; i++)
#pragma unroll
                for (int p = 0; p < 4; p++) ffma2(acc[i][p], a2[i], b2[p]);
        }
        __syncthreads();   // next-tile stores visible; current buffer reusable
        buf ^= 1;
    }

    const float4 bs0 = *(const float4*)&bias[col0 + tx * 8];
    const float4 bs1 = *(const float4*)&bias[col0 + tx * 8 + 4];
#pragma unroll
    for (int i = 0; i < 4; i++) {
        float o[8];
#pragma unroll
        for (int p = 0; p < 4; p++) unpack2(o[2 * p], o[2 * p + 1], acc[i][p]);
        float* cp = &C[(size_t)(row0 + ty * 4 + i) * DM_ + col0 + tx * 8];
        *(float4*)cp       = make_float4(o[0] + bs0.x, o[1] + bs0.y, o[2] + bs0.z, o[3] + bs0.w);
        *(float4*)(cp + 4) = make_float4(o[4] + bs1.x, o[5] + bs1.y, o[6] + bs1.z, o[7] + bs1.w);
    }
}

// Fused QKV projection: blockIdx.z selects which projection this block does.
__global__ __launch_bounds__(256) void qkv_proj_k(
    const float* __restrict__ Qi, const float* __restrict__ Ki, const float* __restrict__ Vi,
    const float* __restrict__ Wq, const float* __restrict__ bq,
    const float* __restrict__ Wk, const float* __restrict__ bk,
    const float* __restrict__ Wv, const float* __restrict__ bv) {
    const int z = blockIdx.z;
    const float* A    = (z == 0) ? Qi : (z == 1) ? Ki : Vi;
    const float* W    = (z == 0) ? Wq : (z == 1) ? Wk : Wv;
    const float* bias = (z == 0) ? bq : (z == 1) ? bk : bv;
    float* C          = (z == 0) ? g_q : (z == 1) ? g_k : g_v;
    gemm_bias_body(A, W, bias, C);
}

// Output projection.
__global__ __launch_bounds__(256) void out_proj_k(
    const float* __restrict__ Wo, const float* __restrict__ bo, float* __restrict__ out) {
    gemm_bias_body(g_attn, Wo, bo, out);
}

// ---------------------------------------------------------------------------
// Scores + exp: E[bh,q,kk] = exp((q.k)/8), plus deterministic per-block row
// partial sums into g_psum. 64x128 tile, K=64 (full depth, one smem load).
// ---------------------------------------------------------------------------
__global__ __launch_bounds__(256) void scores_k(float* __restrict__ E) {
    union Smem {
        struct { float Qs[64][64]; float Ks[64][128]; } t;  // 48 KB
        float red[64][17];
    };
    __shared__ Smem sm;
    const int bh = blockIdx.z;
    const int b = bh >> 4, h = bh & 15;
    const float* qb = g_q + (size_t)b * S_ * DM_ + h * D_;
    const float* kb = g_k + (size_t)b * S_ * DM_ + h * D_;
    const int tid = threadIdx.x;
    const int tx = tid & 15, ty = tid >> 4;
    const int row0 = blockIdx.y * 64, col0 = blockIdx.x * 128;

    {   // load Q tile [64 rows][64 k] (row-major, float4)
        const int lm = tid >> 2, lkq = (tid & 3) << 4;
#pragma unroll
        for (int v = 0; v < 4; v++)
            *(float4*)&sm.t.Qs[lm][lkq + 4 * v] =
                *(const float4*)&qb[(size_t)(row0 + lm) * DM_ + lkq + 4 * v];
    }
    {   // load K tile [128 cols][64 k] transposed into [k][n]
        const int ln = tid >> 1, lkk = (tid & 1) << 5;
#pragma unroll
        for (int v = 0; v < 8; v++) {
            float4 kv = *(const float4*)&kb[(size_t)(col0 + ln) * DM_ + lkk + 4 * v];
            sm.t.Ks[lkk + 4 * v + 0][ln] = kv.x;
            sm.t.Ks[lkk + 4 * v + 1][ln] = kv.y;
            sm.t.Ks[lkk + 4 * v + 2][ln] = kv.z;
            sm.t.Ks[lkk + 4 * v + 3][ln] = kv.w;
        }
    }
    __syncthreads();

    u64 acc[4][4];
#pragma unroll
    for (int i = 0; i < 4; i++)
#pragma unroll
        for (int p = 0; p < 4; p++) acc[i][p] = 0ull;

#pragma unroll 16
    for (int k = 0; k < 64; k++) {
        u64 a2[4];
#pragma unroll
        for (int i = 0; i < 4; i++) a2[i] = pack2(sm.t.Qs[ty * 4 + i][k]);
        const u64* bp = (const u64*)&sm.t.Ks[k][tx * 8];
        ulonglong2 bb0 = *(const ulonglong2*)bp;
        ulonglong2 bb1 = *(const ulonglong2*)(bp + 2);
        u64 b2[4] = {bb0.x, bb0.y, bb1.x, bb1.y};
#pragma unroll
        for (int i = 0; i < 4; i++)
#pragma unroll
            for (int p = 0; p < 4; p++) ffma2(acc[i][p], a2[i], b2[p]);
    }
    __syncthreads();   // Qs/Ks dead; red may alias

    float e[4][8], rsum[4];
#pragma unroll
    for (int i = 0; i < 4; i++) {
        rsum[i] = 0.f;
#pragma unroll
        for (int p = 0; p < 4; p++) {
            float lo, hi; unpack2(lo, hi, acc[i][p]);
            e[i][2 * p]     = __expf(lo * 0.125f);
            e[i][2 * p + 1] = __expf(hi * 0.125f);
            rsum[i] += e[i][2 * p] + e[i][2 * p + 1];
        }
        float* ep = &E[((size_t)bh * S_ + row0 + ty * 4 + i) * S_ + col0 + tx * 8];
        *(float4*)ep       = make_float4(e[i][0], e[i][1], e[i][2], e[i][3]);
        *(float4*)(ep + 4) = make_float4(e[i][4], e[i][5], e[i][6], e[i][7]);
        sm.red[ty * 4 + i][tx] = rsum[i];
    }
    __syncthreads();
    if (tid < 64) {
        float s = 0.f;
#pragma unroll
        for (int p = 0; p < 16; p++) s += sm.red[tid][p];
        g_psum[((size_t)bh * S_ + row0 + tid) * 16 + blockIdx.x] = s;
    }
}

// ---------------------------------------------------------------------------
// Normalize + attn@V: reads E, writes weights = E/rowsum in place, and
// accumulates attn = weights @ V_head into concat layout. 128 threads,
// 64 rows x 64 cols, K tiles of 16 over 2048. Double-buffered smem.
// ---------------------------------------------------------------------------
__global__ __launch_bounds__(128) void attnv_k(float* __restrict__ Wt) {
    __shared__ float Es[2][64][16];   // [buf] normalized weights tile [m][k]
    __shared__ float Vs[2][16][64];   // [buf] [k][n]
    __shared__ float sinv[64];
    const int bh = blockIdx.y;
    const int b = bh >> 4, h = bh & 15;
    const int row0 = blockIdx.x * 64;
    const int tid = threadIdx.x;
    const int tx = tid & 7, ty = tid >> 3;

    if (tid < 64) {
        const float* pp = &g_psum[((size_t)bh * S_ + row0 + tid) * 16];
        float s = 0.f;
#pragma unroll
        for (int p = 0; p < 16; p++) s += pp[p];
        sinv[tid] = 1.0f / s;
    }
    __syncthreads();

    const int lm = tid >> 1, lk8 = (tid & 1) << 3;   // E loader: row, k-offset
    const int kv = tid >> 3, n8 = (tid & 7) << 3;    // V loader
    const float linv = sinv[lm];
    float* wrow = Wt + (size_t)bh * S_ * S_ + (size_t)(row0 + lm) * S_ + lk8;
    const float* vb = g_v + (size_t)b * S_ * DM_ + h * D_;

    u64 acc[4][4];
#pragma unroll
    for (int i = 0; i < 4; i++)
#pragma unroll
        for (int p = 0; p < 4; p++) acc[i][p] = 0ull;

    // Prologue: tile 0 into buffer 0 (normalize + write weights + stage smem).
    {
        float4 e0 = *(const float4*)(wrow);
        float4 e1 = *(const float4*)(wrow + 4);
        float4 w0 = make_float4(e0.x * linv, e0.y * linv, e0.z * linv, e0.w * linv);
        float4 w1 = make_float4(e1.x * linv, e1.y * linv, e1.z * linv, e1.w * linv);
        *(float4*)(wrow)     = w0;
        *(float4*)(wrow + 4) = w1;
        *(float4*)&Es[0][lm][lk8]     = w0;
        *(float4*)&Es[0][lm][lk8 + 4] = w1;
        *(float4*)&Vs[0][kv][n8]     = *(const float4*)&vb[(size_t)kv * DM_ + n8];
        *(float4*)&Vs[0][kv][n8 + 4] = *(const float4*)&vb[(size_t)kv * DM_ + n8 + 4];
    }
    __syncthreads();

    int buf = 0;
    for (int kt = 0; kt < S_; kt += 16) {
        // Stage next tile into the other buffer (and do its weights write).
        if (kt + 16 < S_) {
            float4 e0 = *(const float4*)(wrow + kt + 16);
            float4 e1 = *(const float4*)(wrow + kt + 20);
            float4 w0 = make_float4(e0.x * linv, e0.y * linv, e0.z * linv, e0.w * linv);
            float4 w1 = make_float4(e1.x * linv, e1.y * linv, e1.z * linv, e1.w * linv);
            *(float4*)(wrow + kt + 16) = w0;
            *(float4*)(wrow + kt + 20) = w1;
            *(float4*)&Es[buf ^ 1][lm][lk8]     = w0;
            *(float4*)&Es[buf ^ 1][lm][lk8 + 4] = w1;
            *(float4*)&Vs[buf ^ 1][kv][n8]     = *(const float4*)&vb[(size_t)(kt + 16 + kv) * DM_ + n8];
            *(float4*)&Vs[buf ^ 1][kv][n8 + 4] = *(const float4*)&vb[(size_t)(kt + 16 + kv) * DM_ + n8 + 4];
        }
        // Compute on current buffer.
#pragma unroll
        for (int k = 0; k < 16; k++) {
            u64 a2[4];
#pragma unroll
            for (int i = 0; i < 4; i++) a2[i] = pack2(Es[buf][ty * 4 + i][k]);
            const u64* bp = (const u64*)&Vs[buf][k][tx * 8];
            ulonglong2 bb0 = *(const ulonglong2*)bp;
            ulonglong2 bb1 = *(const ulonglong2*)(bp + 2);
            u64 b2[4] = {bb0.x, bb0.y, bb1.x, bb1.y};
#pragma unroll
            for (int i = 0; i < 4; i++)
#pragma unroll
                for (int p = 0; p < 4; p++) ffma2(acc[i][p], a2[i], b2[p]);
        }
        __syncthreads();
        buf ^= 1;
    }
    float* ob = g_attn + (size_t)b * S_ * DM_ + h * D_;
#pragma unroll
    for (int i = 0; i < 4; i++) {
        float o[8];
#pragma unroll
        for (int p = 0; p < 4; p++) unpack2(o[2 * p], o[2 * p + 1], acc[i][p]);
        float* op = &ob[(size_t)(row0 + ty * 4 + i) * DM_ + tx * 8];
        *(float4*)op       = make_float4(o[0], o[1], o[2], o[3]);
        *(float4*)(op + 4) = make_float4(o[4], o[5], o[6], o[7]);
    }
}

// ---------------------------------------------------------------------------
extern "C" void kernel_launch(void* const* d_in, const int* in_sizes, int n_in,
                              void* d_out, int out_size) {
    const float* Qi = (const float*)d_in[0];
    const float* Ki = (const float*)d_in[1];
    const float* Vi = (const float*)d_in[2];
    const float* Wq = (const float*)d_in[3];
    const float* bq = (const float*)d_in[4];
    const float* Wk = (const float*)d_in[5];
    const float* bk = (const float*)d_in[6];
    const float* Wv = (const float*)d_in[7];
    const float* bv = (const float*)d_in[8];
    const float* Wo = (const float*)d_in[9];
    const float* bo = (const float*)d_in[10];

    float* out = (float*)d_out;                   // [B,S,DM]
    float* wts = out + (size_t)B_ * S_ * DM_;     // [B,H,S,S]

    dim3 gproj(DM_ / 128, MTOT / 64, 3);          // (8, 64, 3) — fused QKV

    qkv_proj_k<<<gproj, 256>>>(Qi, Ki, Vi, Wq, bq, Wk, bk, Wv, bv);
    scores_k<<<dim3(S_ / 128, S_ / 64, B_ * H_), 256>>>(wts);
    attnv_k<<<dim3(S_ / 64, B_ * H_), 128>>>(wts);
    out_proj_k<<<dim3(DM_ / 128, MTOT / 64), 256>>>(Wo, bo, out);
}

// round 14
// speedup vs baseline: 1.0256x; 1.0256x over previous
#include <cuda_runtime.h>
#include <math.h>

#define B_   2
#define S_   2048
#define DM_  1024
#define H_   16
#define D_   64
#define MTOT (B_ * S_)   // 4096

// Scratch (no cudaMalloc allowed).
__device__ float g_q[B_ * S_ * DM_];
__device__ float g_k[B_ * S_ * DM_];
__device__ float g_v[B_ * S_ * DM_];
__device__ float g_attn[B_ * S_ * DM_];
__device__ float g_psum[B_ * H_ * S_ * 16];   // per-(row, col-tile) partial exp sums

// ---------------------------------------------------------------------------
// GEMM + bias body: C[4096,1024] = A[4096,1024] @ W[1024,1024] + bias.
// 64x128 tile, 256 threads, 4x8 per-thread tile, SCALAR fp32 FFMA.
// Double-buffered smem ping-pong hides global-load latency.
// ---------------------------------------------------------------------------
__device__ __forceinline__ void gemm_bias_body(
    const float* __restrict__ A, const float* __restrict__ W,
    const float* __restrict__ bias, float* __restrict__ C) {
    __shared__ float As[2][64][16];    // [buf][m][k]
    __shared__ float Bs[2][16][128];   // [buf][k][n]
    const int tid = threadIdx.x;
    const int tx = tid & 15, ty = tid >> 4;
    const int row0 = blockIdx.y * 64, col0 = blockIdx.x * 128;
    const int lm = tid >> 2, lk4 = (tid & 3) << 2;   // A loader
    const int lkb = tid >> 4, ln8 = (tid & 15) << 3; // B loader

    const float* aptr = &A[(size_t)(row0 + lm) * DM_ + lk4];
    const float* wptr = &W[(size_t)lkb * DM_ + col0 + ln8];

    float acc[4][8];
#pragma unroll
    for (int i = 0; i < 4; i++)
#pragma unroll
        for (int j = 0; j < 8; j++) acc[i][j] = 0.f;

    // Prologue: load tile 0 into buffer 0.
    *(float4*)&As[0][lm][lk4]       = *(const float4*)aptr;
    *(float4*)&Bs[0][lkb][ln8]      = *(const float4*)wptr;
    *(float4*)&Bs[0][lkb][ln8 + 4]  = *(const float4*)(wptr + 4);
    __syncthreads();

    int buf = 0;
    for (int kt = 0; kt < DM_; kt += 16) {
        if (kt + 16 < DM_) {
            const float* an = aptr + kt + 16;
            const float* wn = wptr + (size_t)(kt + 16) * DM_;
            *(float4*)&As[buf ^ 1][lm][lk4]      = *(const float4*)an;
            *(float4*)&Bs[buf ^ 1][lkb][ln8]     = *(const float4*)wn;
            *(float4*)&Bs[buf ^ 1][lkb][ln8 + 4] = *(const float4*)(wn + 4);
        }
#pragma unroll
        for (int k = 0; k < 16; k++) {
            float a[4];
#pragma unroll
            for (int i = 0; i < 4; i++) a[i] = As[buf][ty * 4 + i][k];
            float b[8];
            *(float4*)&b[0] = *(const float4*)&Bs[buf][k][tx * 8];
            *(float4*)&b[4] = *(const float4*)&Bs[buf][k][tx * 8 + 4];
#pragma unroll
            for (int i = 0; i < 4; i++)
#pragma unroll
                for (int j = 0; j < 8; j++) acc[i][j] += a[i] * b[j];
        }
        __syncthreads();
        buf ^= 1;
    }

    const float4 bs0 = *(const float4*)&bias[col0 + tx * 8];
    const float4 bs1 = *(const float4*)&bias[col0 + tx * 8 + 4];
#pragma unroll
    for (int i = 0; i < 4; i++) {
        float* cp = &C[(size_t)(row0 + ty * 4 + i) * DM_ + col0 + tx * 8];
        *(float4*)cp       = make_float4(acc[i][0] + bs0.x, acc[i][1] + bs0.y,
                                         acc[i][2] + bs0.z, acc[i][3] + bs0.w);
        *(float4*)(cp + 4) = make_float4(acc[i][4] + bs1.x, acc[i][5] + bs1.y,
                                         acc[i][6] + bs1.z, acc[i][7] + bs1.w);
    }
}

// Fused QKV projection: blockIdx.z selects which projection this block does.
__global__ __launch_bounds__(256) void qkv_proj_k(
    const float* __restrict__ Qi, const float* __restrict__ Ki, const float* __restrict__ Vi,
    const float* __restrict__ Wq, const float* __restrict__ bq,
    const float* __restrict__ Wk, const float* __restrict__ bk,
    const float* __restrict__ Wv, const float* __restrict__ bv) {
    const int z = blockIdx.z;
    const float* A    = (z == 0) ? Qi : (z == 1) ? Ki : Vi;
    const float* W    = (z == 0) ? Wq : (z == 1) ? Wk : Wv;
    const float* bias = (z == 0) ? bq : (z == 1) ? bk : bv;
    float* C          = (z == 0) ? g_q : (z == 1) ? g_k : g_v;
    gemm_bias_body(A, W, bias, C);
}

// Output projection.
__global__ __launch_bounds__(256) void out_proj_k(
    const float* __restrict__ Wo, const float* __restrict__ bo, float* __restrict__ out) {
    gemm_bias_body(g_attn, Wo, bo, out);
}

// ---------------------------------------------------------------------------
// Scores + exp: E[bh,q,kk] = exp((q.k)/8), plus deterministic per-block row
// partial sums into g_psum. 64x128 tile, K=64 (full depth, one smem load).
// ---------------------------------------------------------------------------
__global__ __launch_bounds__(256) void scores_k(float* __restrict__ E) {
    union Smem {
        struct { float Qs[64][64]; float Ks[64][128]; } t;  // 48 KB
        float red[64][17];
    };
    __shared__ Smem sm;
    const int bh = blockIdx.z;
    const int b = bh >> 4, h = bh & 15;
    const float* qb = g_q + (size_t)b * S_ * DM_ + h * D_;
    const float* kb = g_k + (size_t)b * S_ * DM_ + h * D_;
    const int tid = threadIdx.x;
    const int tx = tid & 15, ty = tid >> 4;
    const int row0 = blockIdx.y * 64, col0 = blockIdx.x * 128;

    {   // load Q tile [64 rows][64 k] (row-major, float4)
        const int lm = tid >> 2, lkq = (tid & 3) << 4;
#pragma unroll
        for (int v = 0; v < 4; v++)
            *(float4*)&sm.t.Qs[lm][lkq + 4 * v] =
                *(const float4*)&qb[(size_t)(row0 + lm) * DM_ + lkq + 4 * v];
    }
    {   // load K tile [128 cols][64 k] transposed into [k][n]
        const int ln = tid >> 1, lkk = (tid & 1) << 5;
#pragma unroll
        for (int v = 0; v < 8; v++) {
            float4 kv = *(const float4*)&kb[(size_t)(col0 + ln) * DM_ + lkk + 4 * v];
            sm.t.Ks[lkk + 4 * v + 0][ln] = kv.x;
            sm.t.Ks[lkk + 4 * v + 1][ln] = kv.y;
            sm.t.Ks[lkk + 4 * v + 2][ln] = kv.z;
            sm.t.Ks[lkk + 4 * v + 3][ln] = kv.w;
        }
    }
    __syncthreads();

    float acc[4][8];
#pragma unroll
    for (int i = 0; i < 4; i++)
#pragma unroll
        for (int j = 0; j < 8; j++) acc[i][j] = 0.f;

#pragma unroll 16
    for (int k = 0; k < 64; k++) {
        float a[4];
#pragma unroll
        for (int i = 0; i < 4; i++) a[i] = sm.t.Qs[ty * 4 + i][k];
        float b[8];
        *(float4*)&b[0] = *(const float4*)&sm.t.Ks[k][tx * 8];
        *(float4*)&b[4] = *(const float4*)&sm.t.Ks[k][tx * 8 + 4];
#pragma unroll
        for (int i = 0; i < 4; i++)
#pragma unroll
            for (int j = 0; j < 8; j++) acc[i][j] += a[i] * b[j];
    }
    __syncthreads();   // Qs/Ks dead; red may alias

    float rsum[4];
#pragma unroll
    for (int i = 0; i < 4; i++) {
        float e[8];
        rsum[i] = 0.f;
#pragma unroll
        for (int j = 0; j < 8; j++) {
            e[j] = __expf(acc[i][j] * 0.125f);
            rsum[i] += e[j];
        }
        float* ep = &E[((size_t)bh * S_ + row0 + ty * 4 + i) * S_ + col0 + tx * 8];
        *(float4*)ep       = make_float4(e[0], e[1], e[2], e[3]);
        *(float4*)(ep + 4) = make_float4(e[4], e[5], e[6], e[7]);
        sm.red[ty * 4 + i][tx] = rsum[i];
    }
    __syncthreads();
    if (tid < 64) {
        float s = 0.f;
#pragma unroll
        for (int p = 0; p < 16; p++) s += sm.red[tid][p];
        g_psum[((size_t)bh * S_ + row0 + tid) * 16 + blockIdx.x] = s;
    }
}

// ---------------------------------------------------------------------------
// Normalize + attn@V: reads E, writes weights = E/rowsum in place, and
// accumulates attn = weights @ V_head into concat layout. 128 threads,
// 64 rows x 64 cols, K tiles of 16 over 2048. Double-buffered smem.
// ---------------------------------------------------------------------------
__global__ __launch_bounds__(128) void attnv_k(float* __restrict__ Wt) {
    __shared__ float Es[2][64][16];   // [buf] normalized weights tile [m][k]
    __shared__ float Vs[2][16][64];   // [buf] [k][n]
    __shared__ float sinv[64];
    const int bh = blockIdx.y;
    const int b = bh >> 4, h = bh & 15;
    const int row0 = blockIdx.x * 64;
    const int tid = threadIdx.x;
    const int tx = tid & 7, ty = tid >> 3;

    if (tid < 64) {
        const float* pp = &g_psum[((size_t)bh * S_ + row0 + tid) * 16];
        float s = 0.f;
#pragma unroll
        for (int p = 0; p < 16; p++) s += pp[p];
        sinv[tid] = 1.0f / s;
    }
    __syncthreads();

    const int lm = tid >> 1, lk8 = (tid & 1) << 3;   // E loader: row, k-offset
    const int kv = tid >> 3, n8 = (tid & 7) << 3;    // V loader
    const float linv = sinv[lm];
    float* wrow = Wt + (size_t)bh * S_ * S_ + (size_t)(row0 + lm) * S_ + lk8;
    const float* vb = g_v + (size_t)b * S_ * DM_ + h * D_;

    float acc[4][8];
#pragma unroll
    for (int i = 0; i < 4; i++)
#pragma unroll
        for (int j = 0; j < 8; j++) acc[i][j] = 0.f;

    // Prologue: tile 0 into buffer 0 (normalize + write weights + stage smem).
    {
        float4 e0 = *(const float4*)(wrow);
        float4 e1 = *(const float4*)(wrow + 4);
        float4 w0 = make_float4(e0.x * linv, e0.y * linv, e0.z * linv, e0.w * linv);
        float4 w1 = make_float4(e1.x * linv, e1.y * linv, e1.z * linv, e1.w * linv);
        *(float4*)(wrow)     = w0;
        *(float4*)(wrow + 4) = w1;
        *(float4*)&Es[0][lm][lk8]     = w0;
        *(float4*)&Es[0][lm][lk8 + 4] = w1;
        *(float4*)&Vs[0][kv][n8]     = *(const float4*)&vb[(size_t)kv * DM_ + n8];
        *(float4*)&Vs[0][kv][n8 + 4] = *(const float4*)&vb[(size_t)kv * DM_ + n8 + 4];
    }
    __syncthreads();

    int buf = 0;
    for (int kt = 0; kt < S_; kt += 16) {
        if (kt + 16 < S_) {
            float4 e0 = *(const float4*)(wrow + kt + 16);
            float4 e1 = *(const float4*)(wrow + kt + 20);
            float4 w0 = make_float4(e0.x * linv, e0.y * linv, e0.z * linv, e0.w * linv);
            float4 w1 = make_float4(e1.x * linv, e1.y * linv, e1.z * linv, e1.w * linv);
            *(float4*)(wrow + kt + 16) = w0;
            *(float4*)(wrow + kt + 20) = w1;
            *(float4*)&Es[buf ^ 1][lm][lk8]     = w0;
            *(float4*)&Es[buf ^ 1][lm][lk8 + 4] = w1;
            *(float4*)&Vs[buf ^ 1][kv][n8]     = *(const float4*)&vb[(size_t)(kt + 16 + kv) * DM_ + n8];
            *(float4*)&Vs[buf ^ 1][kv][n8 + 4] = *(const float4*)&vb[(size_t)(kt + 16 + kv) * DM_ + n8 + 4];
        }
#pragma unroll
        for (int k = 0; k < 16; k++) {
            float a[4];
#pragma unroll
            for (int i = 0; i < 4; i++) a[i] = Es[buf][ty * 4 + i][k];
            float b[8];
            *(float4*)&b[0] = *(const float4*)&Vs[buf][k][tx * 8];
            *(float4*)&b[4] = *(const float4*)&Vs[buf][k][tx * 8 + 4];
#pragma unroll
            for (int i = 0; i < 4; i++)
#pragma unroll
                for (int j = 0; j < 8; j++) acc[i][j] += a[i] * b[j];
        }
        __syncthreads();
        buf ^= 1;
    }
    float* ob = g_attn + (size_t)b * S_ * DM_ + h * D_;
#pragma unroll
    for (int i = 0; i < 4; i++) {
        float* op = &ob[(size_t)(row0 + ty * 4 + i) * DM_ + tx * 8];
        *(float4*)op       = make_float4(acc[i][0], acc[i][1], acc[i][2], acc[i][3]);
        *(float4*)(op + 4) = make_float4(acc[i][4], acc[i][5], acc[i][6], acc[i][7]);
    }
}

// ---------------------------------------------------------------------------
extern "C" void kernel_launch(void* const* d_in, const int* in_sizes, int n_in,
                              void* d_out, int out_size) {
    const float* Qi = (const float*)d_in[0];
    const float* Ki = (const float*)d_in[1];
    const float* Vi = (const float*)d_in[2];
    const float* Wq = (const float*)d_in[3];
    const float* bq = (const float*)d_in[4];
    const float* Wk = (const float*)d_in[5];
    const float* bk = (const float*)d_in[6];
    const float* Wv = (const float*)d_in[7];
    const float* bv = (const float*)d_in[8];
    const float* Wo = (const float*)d_in[9];
    const float* bo = (const float*)d_in[10];

    float* out = (float*)d_out;                   // [B,S,DM]
    float* wts = out + (size_t)B_ * S_ * DM_;     // [B,H,S,S]

    dim3 gproj(DM_ / 128, MTOT / 64, 3);          // (8, 64, 3) — fused QKV

    qkv_proj_k<<<gproj, 256>>>(Qi, Ki, Vi, Wq, bq, Wk, bk, Wv, bv);
    scores_k<<<dim3(S_ / 128, S_ / 64, B_ * H_), 256>>>(wts);
    attnv_k<<<dim3(S_ / 64, B_ * H_), 128>>>(wts);
    out_proj_k<<<dim3(DM_ / 128, MTOT / 64), 256>>>(Wo, bo, out);
}